// round 11
// baseline (speedup 1.0000x reference)
#include <cuda_runtime.h>
#include <cuda_bf16.h>
#include <cstdint>

// Problem constants (fixed by the dataset)
#define B_  8
#define S_  4096
#define D_  1024
#define H_  16
#define HD_ 64
#define NR_ 32
#define ROWS_ (B_ * S_ * H_)        // 524288
#define WROWS 32                     // rows per WARP tile
#define NTILES (ROWS_ / WROWS)       // 16384
#define WARPS_PB 4
#define TPB 128
#define PITCH 69                     // bank multiplier 5 (odd)

// per-row-class pad before columns >= 32: b = {3,1,2,2}
// (verified conflict-free for stage-in class pairs (0,1)/(2,3), Givens
// uniform-column access at multiplier 5, and the remix read pattern)
__device__ __forceinline__ int bpad(int p) { return (0x2213 >> (p * 4)) & 0xF; }

// Precomputed RoPE table: per s, 32 cos then 32 sin (64 floats)
__device__ float  g_tab[S_ * 64];
// Packed Givens params: [k][class] = {c, s, bitcast(oi | oj<<16), 0}
__device__ float4 g_param[NR_ * 4];
__device__ int    g_identity;

// ---------------------------------------------------------------------------
// Table + params + identity, one kernel. Double-precision range reduction
// keeps sincosf on its fast path while matching accurate results to ~1e-13.
// ---------------------------------------------------------------------------
__global__ __launch_bounds__(256)
void prep_kernel(const float* __restrict__ inv_freq,
                 const float* __restrict__ thetas,
                 const float* __restrict__ r_pairs,
                 const float* __restrict__ theta_scale,
                 const float* __restrict__ r_matrix) {
    const int t = threadIdx.x;
    int idx = blockIdx.x * 256 + t;                  // [0, S_*32)
    if (idx < S_ * NR_) {
        int s = idx >> 5;
        int k = idx & 31;
        const double TWO_PI = 6.283185307179586476925286766559;
        double a = (double)s * (double)inv_freq[k];
        double r = a - TWO_PI * floor(a / TWO_PI);   // [0, 2pi): fast-path arg
        float sv, cv;
        sincosf((float)r, &sv, &cv);
        g_tab[s * 64 + k]      = cv;
        g_tab[s * 64 + 32 + k] = sv;
    }

    if (blockIdx.x == 0) {
        // Givens params: 128 threads -> 32 rotations x 4 row classes
        if (t < 128) {
            int k = t & 31, p = t >> 5;
            float th = thetas[k] * theta_scale[0];
            float sv, cv;
            sincosf(th, &sv, &cv);
            int i = (int)r_pairs[2 * k];
            int j = (int)r_pairs[2 * k + 1];
            if (i < 0) i = 0; if (i > HD_ - 1) i = HD_ - 1;
            if (j < 0) j = 0; if (j > HD_ - 1) j = HD_ - 1;
            if (i == j) sv = 0.0f;                   // makes general form exact
            int oi = i + ((i >= 32) ? bpad(p) : 0);
            int oj = j + ((j >= 32) ? bpad(p) : 0);
            float4 q;
            q.x = cv; q.y = sv;
            q.z = __int_as_float(oi | (oj << 16));
            q.w = 0.0f;
            g_param[k * 4 + p] = q;
        }
        // identity check: 4096 elements, 16 per thread
        int ok = 1;
        const float4* rm4 = (const float4*)r_matrix;
        #pragma unroll
        for (int kk = 0; kk < 4; kk++) {
            int q = kk * 256 + t;
            float4 v = rm4[q];
            int e = q * 4;
            ok &= (v.x == (((e + 0) >> 6) == ((e + 0) & 63) ? 1.0f : 0.0f));
            ok &= (v.y == (((e + 1) >> 6) == ((e + 1) & 63) ? 1.0f : 0.0f));
            ok &= (v.z == (((e + 2) >> 6) == ((e + 2) & 63) ? 1.0f : 0.0f));
            ok &= (v.w == (((e + 3) >> 6) == ((e + 3) & 63) ? 1.0f : 0.0f));
        }
        int allok = __syncthreads_and(ok);
        if (t == 0) g_identity = allok;
    }
}

// ---------------------------------------------------------------------------
// Warp-autonomous main kernel: each warp owns one 32-row tile; single cheap
// block barrier at start, then warps free-run.
// ---------------------------------------------------------------------------
__global__ __launch_bounds__(TPB, 6)
void rotary_warp_kernel(const float* __restrict__ x,
                        const float* __restrict__ r_matrix,
                        float* __restrict__ out) {
    __shared__ float sm[WARPS_PB][WROWS * PITCH];        // 35,328 B
    __shared__ __align__(16) float4 spar[NR_ * 4];       // 2 KB packed params

    const int t = threadIdx.x;
    const int w = t >> 5;
    const int l = t & 31;

    // ---- cheap prologue: copy param table, read identity flag -------------
    spar[t] = g_param[t];
    const int identity = g_identity;                     // L2 broadcast
    __syncthreads();                                     // only block barrier

    // ---- warp tile ---------------------------------------------------------
    const int tile = blockIdx.x * WARPS_PB + w;          // exact cover
    float* buf = sm[w];
    const float4* gx4 = (const float4*)(x + (size_t)tile * (WROWS * HD_));

    // remix lane constants
    const int jj = l & 7;
    const int rslot = l >> 3;                            // 0..3
    const int off0 = 8 * jj + ((jj >= 4) ? bpad(rslot) : 0);

    // issue the 4 RoPE-table vector loads EARLY (L2 latency hidden by Givens)
    const int s0 = (tile * 2) & (S_ - 1);                // row/16 mod S
    const float4* tg = (const float4*)g_tab;             // 16 float4 per s
    float4 cv0 = tg[s0 * 16 + jj];
    float4 sv0 = tg[s0 * 16 + 8 + jj];
    float4 cv1 = tg[(s0 + 1) * 16 + jj];
    float4 sv1 = tg[(s0 + 1) * 16 + 8 + jj];

    // ---- stage-in: 32x64 floats, 16 LDG.128 -> 64 STS.32 (two batches) ----
    #pragma unroll
    for (int h = 0; h < 2; h++) {
        float4 v[8];
        #pragma unroll
        for (int it = 0; it < 8; it++)
            v[it] = gx4[l + 32 * (8 * h + it)];
        #pragma unroll
        for (int it = 0; it < 8; it++) {
            int q = l + 32 * (8 * h + it);
            int r = q >> 4;
            int c = (q & 15) * 4;
            float* p = &buf[r * PITCH + c + ((c >= 32) ? bpad(r & 3) : 0)];
            p[0] = v[it].x; p[1] = v[it].y; p[2] = v[it].z; p[3] = v[it].w;
        }
    }
    __syncwarp();

    // ---- Givens chain: lane l owns row l ----------------------------------
    {
        float* row = &buf[l * PITCH];
        const int p4 = l & 3;
        #pragma unroll
        for (int k = 0; k < NR_; k++) {
            float4 q = spar[k * 4 + p4];                 // one LDS.128, cf-free
            int pk = __float_as_int(q.z);
            int oi = pk & 0xFFFF, oj = pk >> 16;
            float xi = row[oi];
            float xj = row[oj];
            row[oi] = fmaf(xi, q.x, xj * q.y);
            row[oj] = fmaf(xj, q.x, -xi * q.y);
        }
        // general path: dense r_matrix multiply (not taken when identity)
        if (!identity) {
            const int bp = bpad(p4);
            float y[HD_];
            for (int c2 = 0; c2 < HD_; c2++) {
                float acc = 0.0f;
                for (int k = 0; k < HD_; k++) {
                    int ow = k + ((k >= 32) ? bp : 0);
                    acc = fmaf(row[ow], __ldg(&r_matrix[k * HD_ + c2]), acc);
                }
                y[c2] = acc;
            }
            for (int c2 = 0; c2 < HD_; c2++)
                row[c2 + ((c2 >= 32) ? bp : 0)] = y[c2];
        }
    }
    __syncwarp();

    // ---- fused RoPE remix + coalesced stage-out ---------------------------
    // lane (jj, rslot) computes out[4jj..4jj+3] AND out[+32] for rows
    // r = rslot + 4i (row class == rslot; all banks distinct).
    {
        float4* o4 = (float4*)(out + (size_t)tile * (WROWS * HD_));
        #pragma unroll
        for (int i = 0; i < 8; i++) {
            int r = rslot + 4 * i;
            float4 cv = (i < 4) ? cv0 : cv1;             // s-group: r<16 ? 0 : 1
            float4 sv = (i < 4) ? sv0 : sv1;
            const float* row = &buf[r * PITCH + off0];
            float a0 = row[0], b0 = row[1];
            float a1 = row[2], b1 = row[3];
            float a2 = row[4], b2 = row[5];
            float a3 = row[6], b3 = row[7];
            float4 lo, hi;
            lo.x = a0 * cv.x - b0 * sv.x;  hi.x = a0 * sv.x + b0 * cv.x;
            lo.y = a1 * cv.y - b1 * sv.y;  hi.y = a1 * sv.y + b1 * cv.y;
            lo.z = a2 * cv.z - b2 * sv.z;  hi.z = a2 * sv.z + b2 * cv.z;
            lo.w = a3 * cv.w - b3 * sv.w;  hi.w = a3 * sv.w + b3 * cv.w;
            o4[r * 16 + jj]     = lo;
            o4[r * 16 + 8 + jj] = hi;
        }
    }
}

// ---------------------------------------------------------------------------
extern "C" void kernel_launch(void* const* d_in, const int* in_sizes, int n_in,
                              void* d_out, int out_size) {
    const float* x           = (const float*)d_in[0];
    const float* thetas      = (const float*)d_in[1];
    const float* r_pairs     = (const float*)d_in[2];
    const float* theta_scale = (const float*)d_in[3];
    // d_in[4] = n_rots_scale (unused by reference)
    const float* r_matrix    = (const float*)d_in[5];
    const float* inv_freq    = (const float*)d_in[6];
    float* out = (float*)d_out;

    prep_kernel<<<(S_ * NR_ + 255) / 256, 256>>>(inv_freq, thetas, r_pairs,
                                                 theta_scale, r_matrix);
    rotary_warp_kernel<<<NTILES / WARPS_PB, TPB>>>(x, r_matrix, out);
}